// round 1
// baseline (speedup 1.0000x reference)
#include <cuda_runtime.h>
#include <math.h>

#define BB 128
#define TT 32
#define EE 512
#define HH 512
#define VV 10000
#define CF 2048

// ---------------- scratch (device globals; no allocations allowed) ----------
__device__ float g_h0[BB*HH];
__device__ float g_emb[TT*BB*EE];        // gathered embeddings, [t][b][e]
__device__ float g_XU[TT*BB*HH];         // precomputed emb @ Wu0_x + bu0
__device__ float g_XR[TT*BB*HH];
__device__ float g_XC[TT*BB*HH];
__device__ float g_H0a[BB*HH];           // layer-0 hidden ping-pong
__device__ float g_H0b[BB*HH];
__device__ float g_H1[TT*BB*HH];         // layer-1 hidden per step (feeds logits)
__device__ float g_u[BB*HH];             // per-cell temporaries
__device__ float g_rh[BB*HH];

__device__ __forceinline__ float sigmoidf_(float v){ return 1.f/(1.f+__expf(-v)); }

// ---------------- embedding gather: g_emb[t][b][:] = embedding[tok[b][t]] ---
__global__ void k_gather(const int* __restrict__ tok, const float* __restrict__ emb){
    int row = blockIdx.x;            // t*BB + b
    int t = row >> 7, b = row & 127;
    int v = tok[b*TT + t];
    const float4* src = (const float4*)(emb + (long)v*EE);
    float4* dst = (float4*)(g_emb + (long)row*EE);
    dst[threadIdx.x] = src[threadIdx.x];   // 128 threads x float4 = 512 floats
}

// ---------------- generic 64x64x16 fp32 GEMM, C = epi(A@B + bias) ----------
// EPI: 0 = plain, 1 = tanh, 2 = logits remap ([t*128+b] row -> out[b][t][:])
template<int EPI>
__global__ void k_gemm64(const float* __restrict__ A, const float* __restrict__ Bm,
                         const float* __restrict__ bias, float* __restrict__ C,
                         int M, int N, int K, int lda, int ldb, int ldc)
{
    __shared__ float As[16][68];
    __shared__ float Bs[16][68];
    int tid = threadIdx.x;
    int tx = tid & 15, ty = tid >> 4;
    int m0 = blockIdx.y * 64, n0 = blockIdx.x * 64;
    int arow = tid >> 2, acol = (tid & 3) * 4;
    int brow = tid >> 4, bcol = (tid & 15) * 4;

    float acc[4][4];
#pragma unroll
    for (int i = 0; i < 4; i++)
#pragma unroll
        for (int j = 0; j < 4; j++) acc[i][j] = 0.f;

    const float* Aptr = A + (long)(m0 + arow) * lda + acol;
    const float* Bptr = Bm + (long)brow * ldb + n0 + bcol;
    bool bok = (n0 + bcol) < N;      // N%4==0 so float4 at in-range start is safe

    for (int k0 = 0; k0 < K; k0 += 16){
        float4 av = *(const float4*)(Aptr + k0);
        As[acol+0][arow] = av.x; As[acol+1][arow] = av.y;
        As[acol+2][arow] = av.z; As[acol+3][arow] = av.w;
        float4 bv = bok ? *(const float4*)(Bptr + (long)k0 * ldb)
                        : make_float4(0.f,0.f,0.f,0.f);
        *(float4*)&Bs[brow][bcol] = bv;
        __syncthreads();
#pragma unroll
        for (int kk = 0; kk < 16; kk++){
            float4 a = *(const float4*)&As[kk][ty*4];
            float4 b = *(const float4*)&Bs[kk][tx*4];
            acc[0][0]+=a.x*b.x; acc[0][1]+=a.x*b.y; acc[0][2]+=a.x*b.z; acc[0][3]+=a.x*b.w;
            acc[1][0]+=a.y*b.x; acc[1][1]+=a.y*b.y; acc[1][2]+=a.y*b.z; acc[1][3]+=a.y*b.w;
            acc[2][0]+=a.z*b.x; acc[2][1]+=a.z*b.y; acc[2][2]+=a.z*b.z; acc[2][3]+=a.z*b.w;
            acc[3][0]+=a.w*b.x; acc[3][1]+=a.w*b.y; acc[3][2]+=a.w*b.z; acc[3][3]+=a.w*b.w;
        }
        __syncthreads();
    }

#pragma unroll
    for (int i = 0; i < 4; i++){
        int m = m0 + ty*4 + i;
#pragma unroll
        for (int j = 0; j < 4; j++){
            int n = n0 + tx*4 + j;
            if (n < N){
                float v = acc[i][j] + bias[n];
                if (EPI == 1) v = tanhf(v);
                if (EPI == 2){
                    // row m = t*128 + b  ->  out[b][t][n]
                    C[(long)(m & 127)*(TT*(long)VV) + (long)(m >> 7)*VV + n] = v;
                } else {
                    C[(long)m*ldc + n] = v;
                }
            }
        }
    }
}

// ---------------- GRU u/r kernel: 32x32 tiles, gate chosen by blockIdx.z ----
// PRE=true (layer0): A = h only (K=512), W pointers pre-offset to h-part,
//                    per-element precomputed x-part in xu/xr (includes bias).
// PRE=false (layer1): A = [x | h] (K=1024), full W, bias bu/br.
template<bool PRE>
__global__ void k_gru_ur(const float* __restrict__ x, const float* __restrict__ h,
                         const float* __restrict__ Wu, const float* __restrict__ Wr,
                         const float* __restrict__ bu, const float* __restrict__ br,
                         const float* __restrict__ xu, const float* __restrict__ xr,
                         float* __restrict__ u_out, float* __restrict__ rh_out)
{
    __shared__ float As[32][36];
    __shared__ float Bs[32][36];
    const float* W = (blockIdx.z == 0) ? Wu : Wr;
    int tid = threadIdx.x;
    int tx = tid & 15, ty = tid >> 4;
    int n0 = blockIdx.x * 32, m0 = blockIdx.y * 32;
    int lr = tid >> 3, lc = (tid & 7) * 4;
    float a00=0.f, a01=0.f, a10=0.f, a11=0.f;
    const int KK = PRE ? HH : (EE + HH);

    for (int k0 = 0; k0 < KK; k0 += 32){
        const float* Asrc; int ak;
        if (PRE) { Asrc = h; ak = k0; }
        else if (k0 < EE) { Asrc = x; ak = k0; }
        else { Asrc = h; ak = k0 - EE; }
        *(float4*)&As[lr][lc] = *(const float4*)(Asrc + (long)(m0+lr)*HH + ak + lc);
        *(float4*)&Bs[lr][lc] = *(const float4*)(W + (long)(k0+lr)*HH + n0 + lc);
        __syncthreads();
#pragma unroll
        for (int kk = 0; kk < 32; kk++){
            float av0 = As[ty*2][kk],   av1 = As[ty*2+1][kk];
            float bv0 = Bs[kk][tx*2],   bv1 = Bs[kk][tx*2+1];
            a00 += av0*bv0; a01 += av0*bv1;
            a10 += av1*bv0; a11 += av1*bv1;
        }
        __syncthreads();
    }

    int m = m0 + ty*2, n = n0 + tx*2;
    float accs[2][2] = {{a00,a01},{a10,a11}};
    if (blockIdx.z == 0){
#pragma unroll
        for (int i = 0; i < 2; i++)
#pragma unroll
            for (int j = 0; j < 2; j++){
                int idx = (m+i)*HH + (n+j);
                float p = PRE ? xu[idx] : bu[n+j];
                u_out[idx] = sigmoidf_(accs[i][j] + p);
            }
    } else {
#pragma unroll
        for (int i = 0; i < 2; i++)
#pragma unroll
            for (int j = 0; j < 2; j++){
                int idx = (m+i)*HH + (n+j);
                float p = PRE ? xr[idx] : br[n+j];
                rh_out[idx] = sigmoidf_(accs[i][j] + p) * h[idx];
            }
    }
}

// ---------------- GRU c kernel + blend: h_new = u*h + (1-u)*tanh(...) ------
template<bool PRE>
__global__ void k_gru_c(const float* __restrict__ x, const float* __restrict__ rh,
                        const float* __restrict__ Wc, const float* __restrict__ bc,
                        const float* __restrict__ xc,
                        const float* __restrict__ u, const float* __restrict__ h,
                        float* __restrict__ h_new)
{
    __shared__ float As[32][36];
    __shared__ float Bs[32][36];
    int tid = threadIdx.x;
    int tx = tid & 15, ty = tid >> 4;
    int n0 = blockIdx.x * 32, m0 = blockIdx.y * 32;
    int lr = tid >> 3, lc = (tid & 7) * 4;
    float a00=0.f, a01=0.f, a10=0.f, a11=0.f;
    const int KK = PRE ? HH : (EE + HH);

    for (int k0 = 0; k0 < KK; k0 += 32){
        const float* Asrc; int ak;
        if (PRE) { Asrc = rh; ak = k0; }
        else if (k0 < EE) { Asrc = x; ak = k0; }
        else { Asrc = rh; ak = k0 - EE; }
        *(float4*)&As[lr][lc] = *(const float4*)(Asrc + (long)(m0+lr)*HH + ak + lc);
        *(float4*)&Bs[lr][lc] = *(const float4*)(Wc + (long)(k0+lr)*HH + n0 + lc);
        __syncthreads();
#pragma unroll
        for (int kk = 0; kk < 32; kk++){
            float av0 = As[ty*2][kk],   av1 = As[ty*2+1][kk];
            float bv0 = Bs[kk][tx*2],   bv1 = Bs[kk][tx*2+1];
            a00 += av0*bv0; a01 += av0*bv1;
            a10 += av1*bv0; a11 += av1*bv1;
        }
        __syncthreads();
    }

    int m = m0 + ty*2, n = n0 + tx*2;
    float accs[2][2] = {{a00,a01},{a10,a11}};
#pragma unroll
    for (int i = 0; i < 2; i++)
#pragma unroll
        for (int j = 0; j < 2; j++){
            int idx = (m+i)*HH + (n+j);
            float p = PRE ? xc[idx] : bc[n+j];
            float c = tanhf(accs[i][j] + p);
            float uu = u[idx];
            h_new[idx] = uu * h[idx] + (1.f - uu) * c;
        }
}

// ---------------- final state copy ------------------------------------------
__global__ void k_copy_final(const float* __restrict__ h0f,
                             const float* __restrict__ h1f,
                             float* __restrict__ out)
{
    int i = blockIdx.x * blockDim.x + threadIdx.x;
    if (i < BB*HH){
        out[i]         = h0f[i];
        out[BB*HH + i] = h1f[i];
    }
}

// ---------------- launch ----------------------------------------------------
extern "C" void kernel_launch(void* const* d_in, const int* in_sizes, int n_in,
                              void* d_out, int out_size)
{
    const float* cnn = (const float*)d_in[0];
    const int*   tok = (const int*)  d_in[1];
    const float* emb = (const float*)d_in[2];
    const float* inW = (const float*)d_in[3];
    const float* inb = (const float*)d_in[4];
    const float* Wu0 = (const float*)d_in[5];
    const float* bu0 = (const float*)d_in[6];
    const float* Wr0 = (const float*)d_in[7];
    const float* br0 = (const float*)d_in[8];
    const float* Wc0 = (const float*)d_in[9];
    const float* bc0 = (const float*)d_in[10];
    const float* Wu1 = (const float*)d_in[11];
    const float* bu1 = (const float*)d_in[12];
    const float* Wr1 = (const float*)d_in[13];
    const float* br1 = (const float*)d_in[14];
    const float* Wc1 = (const float*)d_in[15];
    const float* bc1 = (const float*)d_in[16];
    const float* outW= (const float*)d_in[17];
    const float* outb= (const float*)d_in[18];
    float* out = (float*)d_out;

    float *ph0,*pemb,*pXU,*pXR,*pXC,*pH0a,*pH0b,*pH1,*pu,*prh;
    cudaGetSymbolAddress((void**)&ph0,  g_h0);
    cudaGetSymbolAddress((void**)&pemb, g_emb);
    cudaGetSymbolAddress((void**)&pXU,  g_XU);
    cudaGetSymbolAddress((void**)&pXR,  g_XR);
    cudaGetSymbolAddress((void**)&pXC,  g_XC);
    cudaGetSymbolAddress((void**)&pH0a, g_H0a);
    cudaGetSymbolAddress((void**)&pH0b, g_H0b);
    cudaGetSymbolAddress((void**)&pH1,  g_H1);
    cudaGetSymbolAddress((void**)&pu,   g_u);
    cudaGetSymbolAddress((void**)&prh,  g_rh);

    // h0 = tanh(cnn @ in_W + in_b)
    k_gemm64<1><<<dim3(8, 2), 256>>>(cnn, inW, inb, ph0, 128, 512, 2048, 2048, 512, 512);
    // gather embeddings
    k_gather<<<TT*BB, 128>>>(tok, emb);
    // layer-0 x-projections for ALL timesteps (batched, off the serial path)
    k_gemm64<0><<<dim3(8, 64), 256>>>(pemb, Wu0, bu0, pXU, 4096, 512, 512, 512, 512, 512);
    k_gemm64<0><<<dim3(8, 64), 256>>>(pemb, Wr0, br0, pXR, 4096, 512, 512, 512, 512, 512);
    k_gemm64<0><<<dim3(8, 64), 256>>>(pemb, Wc0, bc0, pXC, 4096, 512, 512, 512, 512, 512);

    const float* Wu0h = Wu0 + (long)EE*HH;   // h-part rows of layer-0 weights
    const float* Wr0h = Wr0 + (long)EE*HH;
    const float* Wc0h = Wc0 + (long)EE*HH;

    float* H0prev = ph0;
    float* H1prev = ph0;
    for (int t = 0; t < TT; t++){
        float* H0cur = (t & 1) ? pH0b : pH0a;
        // layer 0 (precomputed x-parts; K=512)
        k_gru_ur<true><<<dim3(16, 4, 2), 256>>>(nullptr, H0prev, Wu0h, Wr0h,
                                                nullptr, nullptr,
                                                pXU + (long)t*BB*HH, pXR + (long)t*BB*HH,
                                                pu, prh);
        k_gru_c<true><<<dim3(16, 4), 256>>>(nullptr, prh, Wc0h, nullptr,
                                            pXC + (long)t*BB*HH, pu, H0prev, H0cur);
        // layer 1 (x = layer-0 output; K=1024)
        float* H1cur = pH1 + (long)t*BB*HH;
        k_gru_ur<false><<<dim3(16, 4, 2), 256>>>(H0cur, H1prev, Wu1, Wr1,
                                                 bu1, br1, nullptr, nullptr,
                                                 pu, prh);
        k_gru_c<false><<<dim3(16, 4), 256>>>(H0cur, prh, Wc1, bc1,
                                             nullptr, pu, H1prev, H1cur);
        H0prev = H0cur; H1prev = H1cur;
    }

    // logits for all timesteps in one GEMM: [4096,512] @ [512,10000]
    k_gemm64<2><<<dim3(157, 64), 256>>>(pH1, outW, outb, out,
                                        4096, VV, 512, 512, VV, VV);
    // final_state = [h_layer0_final, h_layer1_final]
    k_copy_final<<<(BB*HH + 255)/256, 256>>>(H0prev, pH1 + (long)(TT-1)*BB*HH,
                                             out + (long)BB*TT*VV);
}

// round 2
// speedup vs baseline: 1.0175x; 1.0175x over previous
#include <cuda_runtime.h>
#include <math.h>

#define BB 128
#define TT 32
#define EE 512
#define HH 512
#define VV 10000
#define CF 2048
#define NCTA 128

// ---------------- scratch (device globals; no allocations allowed) ----------
__device__ float g_h0[BB*HH];
__device__ float g_emb[TT*BB*EE];        // gathered embeddings, [t][b][e]
__device__ float g_XU[TT*BB*HH];         // precomputed emb @ Wu0_x + bu0
__device__ float g_XR[TT*BB*HH];
__device__ float g_XC[TT*BB*HH];
__device__ float g_H0a[BB*HH];           // layer-0 hidden ping-pong
__device__ float g_H0b[BB*HH];
__device__ float g_H1[TT*BB*HH];         // layer-1 hidden per step (feeds logits)
__device__ float g_u[BB*HH];             // per-cell temporaries
__device__ float g_rh[BB*HH];
__device__ unsigned g_bar;
__device__ unsigned g_gen;

__device__ __forceinline__ float sigmoidf_(float v){ return 1.f/(1.f+__expf(-v)); }

// ---------------- embedding gather ------------------------------------------
__global__ void k_gather(const int* __restrict__ tok, const float* __restrict__ emb){
    int row = blockIdx.x;            // t*BB + b
    int t = row >> 7, b = row & 127;
    int v = tok[b*TT + t];
    const float4* src = (const float4*)(emb + (long)v*EE);
    float4* dst = (float4*)(g_emb + (long)row*EE);
    dst[threadIdx.x] = src[threadIdx.x];
}

// ---------------- generic 64x64x16 fp32 GEMM --------------------------------
// EPI: 1 = tanh, 2 = logits remap ([t*128+b] row -> out[b][t][:])
template<int EPI>
__global__ void k_gemm64(const float* __restrict__ A, const float* __restrict__ Bm,
                         const float* __restrict__ bias, float* __restrict__ C,
                         int M, int N, int K, int lda, int ldb, int ldc)
{
    __shared__ float As[16][68];
    __shared__ float Bs[16][68];
    int tid = threadIdx.x;
    int tx = tid & 15, ty = tid >> 4;
    int m0 = blockIdx.y * 64, n0 = blockIdx.x * 64;
    int arow = tid >> 2, acol = (tid & 3) * 4;
    int brow = tid >> 4, bcol = (tid & 15) * 4;

    float acc[4][4];
#pragma unroll
    for (int i = 0; i < 4; i++)
#pragma unroll
        for (int j = 0; j < 4; j++) acc[i][j] = 0.f;

    const float* Aptr = A + (long)(m0 + arow) * lda + acol;
    const float* Bptr = Bm + (long)brow * ldb + n0 + bcol;
    bool bok = (n0 + bcol) < N;

    for (int k0 = 0; k0 < K; k0 += 16){
        float4 av = *(const float4*)(Aptr + k0);
        As[acol+0][arow] = av.x; As[acol+1][arow] = av.y;
        As[acol+2][arow] = av.z; As[acol+3][arow] = av.w;
        float4 bv = bok ? *(const float4*)(Bptr + (long)k0 * ldb)
                        : make_float4(0.f,0.f,0.f,0.f);
        *(float4*)&Bs[brow][bcol] = bv;
        __syncthreads();
#pragma unroll
        for (int kk = 0; kk < 16; kk++){
            float4 a = *(const float4*)&As[kk][ty*4];
            float4 b = *(const float4*)&Bs[kk][tx*4];
            acc[0][0]+=a.x*b.x; acc[0][1]+=a.x*b.y; acc[0][2]+=a.x*b.z; acc[0][3]+=a.x*b.w;
            acc[1][0]+=a.y*b.x; acc[1][1]+=a.y*b.y; acc[1][2]+=a.y*b.z; acc[1][3]+=a.y*b.w;
            acc[2][0]+=a.z*b.x; acc[2][1]+=a.z*b.y; acc[2][2]+=a.z*b.z; acc[2][3]+=a.z*b.w;
            acc[3][0]+=a.w*b.x; acc[3][1]+=a.w*b.y; acc[3][2]+=a.w*b.z; acc[3][3]+=a.w*b.w;
        }
        __syncthreads();
    }

#pragma unroll
    for (int i = 0; i < 4; i++){
        int m = m0 + ty*4 + i;
#pragma unroll
        for (int j = 0; j < 4; j++){
            int n = n0 + tx*4 + j;
            if (n < N){
                float v = acc[i][j] + bias[n];
                if (EPI == 1) v = tanhf(v);
                if (EPI == 2){
                    C[(long)(m & 127)*(TT*(long)VV) + (long)(m >> 7)*VV + n] = v;
                } else {
                    C[(long)m*ldc + n] = v;
                }
            }
        }
    }
}

// ---------------- fused 3-gate prep GEMM: g_emb @ {Wu0,Wr0,Wc0} + b ---------
__global__ void k_prep3(const float* __restrict__ Wu, const float* __restrict__ Wr,
                        const float* __restrict__ Wc,
                        const float* __restrict__ bu, const float* __restrict__ br,
                        const float* __restrict__ bc)
{
    __shared__ float As[16][68];
    __shared__ float Bs[16][68];
    const float* Bm  = (blockIdx.z==0)? Wu : (blockIdx.z==1)? Wr : Wc;
    const float* bias= (blockIdx.z==0)? bu : (blockIdx.z==1)? br : bc;
    float* C = (blockIdx.z==0)? g_XU : (blockIdx.z==1)? g_XR : g_XC;
    const float* A = g_emb;

    int tid = threadIdx.x;
    int tx = tid & 15, ty = tid >> 4;
    int m0 = blockIdx.y * 64, n0 = blockIdx.x * 64;
    int arow = tid >> 2, acol = (tid & 3) * 4;
    int brow = tid >> 4, bcol = (tid & 15) * 4;

    float acc[4][4];
#pragma unroll
    for (int i = 0; i < 4; i++)
#pragma unroll
        for (int j = 0; j < 4; j++) acc[i][j] = 0.f;

    const float* Aptr = A + (long)(m0 + arow) * EE + acol;
    const float* Bptr = Bm + (long)brow * HH + n0 + bcol;

    for (int k0 = 0; k0 < EE; k0 += 16){
        float4 av = *(const float4*)(Aptr + k0);
        As[acol+0][arow] = av.x; As[acol+1][arow] = av.y;
        As[acol+2][arow] = av.z; As[acol+3][arow] = av.w;
        *(float4*)&Bs[brow][bcol] = *(const float4*)(Bptr + (long)k0 * HH);
        __syncthreads();
#pragma unroll
        for (int kk = 0; kk < 16; kk++){
            float4 a = *(const float4*)&As[kk][ty*4];
            float4 b = *(const float4*)&Bs[kk][tx*4];
            acc[0][0]+=a.x*b.x; acc[0][1]+=a.x*b.y; acc[0][2]+=a.x*b.z; acc[0][3]+=a.x*b.w;
            acc[1][0]+=a.y*b.x; acc[1][1]+=a.y*b.y; acc[1][2]+=a.y*b.z; acc[1][3]+=a.y*b.w;
            acc[2][0]+=a.z*b.x; acc[2][1]+=a.z*b.y; acc[2][2]+=a.z*b.z; acc[2][3]+=a.z*b.w;
            acc[3][0]+=a.w*b.x; acc[3][1]+=a.w*b.y; acc[3][2]+=a.w*b.z; acc[3][3]+=a.w*b.w;
        }
        __syncthreads();
    }

#pragma unroll
    for (int i = 0; i < 4; i++){
        int m = m0 + ty*4 + i;
#pragma unroll
        for (int j = 0; j < 4; j++){
            int n = n0 + tx*4 + j;
            C[(long)m*HH + n] = acc[i][j] + bias[n];
        }
    }
}

// ---------------- barrier state reset (per graph replay) --------------------
__global__ void k_reset(){ g_bar = 0u; g_gen = 0u; }

// ---------------- grid-wide sense barrier -----------------------------------
__device__ __forceinline__ void gsync(unsigned &my_gen){
    __syncthreads();
    if (threadIdx.x == 0){
        __threadfence();
        my_gen++;
        if (atomicAdd(&g_bar, 1u) == NCTA-1u){
            atomicExch(&g_bar, 0u);
            __threadfence();
            atomicExch(&g_gen, my_gen);
        } else {
            while (*(volatile unsigned*)&g_gen < my_gen) { }
            __threadfence();
        }
    }
    __syncthreads();
}

// ---------------- 32x32-tile GEMM body (2x2/thread), A may be [x|h] concat --
__device__ __forceinline__ void mm32(const float* __restrict__ Ax,
                                     const float* __restrict__ Ah,
                                     int KK, const float* __restrict__ W,
                                     int m0, int n0, int tid,
                                     float As[32][36], float Bs[32][36],
                                     float acc[2][2])
{
    int lr = tid >> 3, lc = (tid & 7) * 4;
    int tx = tid & 15, ty = tid >> 4;
    acc[0][0]=acc[0][1]=acc[1][0]=acc[1][1]=0.f;
    for (int k0 = 0; k0 < KK; k0 += 32){
        const float* Asrc = (k0 < EE) ? Ax : Ah;
        int ak = (k0 < EE) ? k0 : k0 - EE;
        *(float4*)&As[lr][lc] = __ldcg((const float4*)(Asrc + (m0+lr)*HH + ak + lc));
        *(float4*)&Bs[lr][lc] = *(const float4*)(W + (k0+lr)*HH + n0 + lc);
        __syncthreads();
#pragma unroll
        for (int kk = 0; kk < 32; kk++){
            float a0 = As[ty*2][kk],  a1 = As[ty*2+1][kk];
            float b0 = Bs[kk][tx*2],  b1 = Bs[kk][tx*2+1];
            acc[0][0] += a0*b0; acc[0][1] += a0*b1;
            acc[1][0] += a1*b0; acc[1][1] += a1*b1;
        }
        __syncthreads();
    }
}

// ---------------- 32x16-tile GEMM body (1x2/thread) -------------------------
__device__ __forceinline__ void mm16(const float* __restrict__ Ax,
                                     const float* __restrict__ Ah,
                                     int KK, const float* __restrict__ W,
                                     int m0, int n0, int tid,
                                     float As[32][36], float Bs[32][36],
                                     float &acc0, float &acc1)
{
    int lr = tid >> 3, lc = (tid & 7) * 4;
    int row = tid >> 3, colp = (tid & 7) * 2;
    acc0 = acc1 = 0.f;
    for (int k0 = 0; k0 < KK; k0 += 32){
        const float* Asrc = (k0 < EE) ? Ax : Ah;
        int ak = (k0 < EE) ? k0 : k0 - EE;
        *(float4*)&As[lr][lc] = __ldcg((const float4*)(Asrc + (m0+lr)*HH + ak + lc));
        if (tid < 128){
            int br = tid >> 2, bc = (tid & 3) * 4;
            *(float4*)&Bs[br][bc] = *(const float4*)(W + (k0+br)*HH + n0 + bc);
        }
        __syncthreads();
#pragma unroll
        for (int kk = 0; kk < 32; kk += 4){
            float4 a = *(const float4*)&As[row][kk];
            acc0 += a.x*Bs[kk][colp]   + a.y*Bs[kk+1][colp]
                  + a.z*Bs[kk+2][colp] + a.w*Bs[kk+3][colp];
            acc1 += a.x*Bs[kk][colp+1]   + a.y*Bs[kk+1][colp+1]
                  + a.z*Bs[kk+2][colp+1] + a.w*Bs[kk+3][colp+1];
        }
        __syncthreads();
    }
}

// ---------------- persistent recurrent kernel: all 32 steps, 2 layers -------
__global__ void __launch_bounds__(256, 1)
k_recurrent(const float* __restrict__ Wu0h, const float* __restrict__ Wr0h,
            const float* __restrict__ Wc0h,
            const float* __restrict__ Wu1,  const float* __restrict__ Wr1,
            const float* __restrict__ Wc1,
            const float* __restrict__ bu1,  const float* __restrict__ br1,
            const float* __restrict__ bc1)
{
    __shared__ float As[32][36];
    __shared__ float Bs[32][36];
    int tid = threadIdx.x, c = blockIdx.x;
    unsigned my_gen = 0;
    int tx = tid & 15, ty = tid >> 4;
    // phase A/C tile map: 2 gates x 4 m-tiles x 16 n-tiles = 128 CTAs
    int gate = c >> 6, rem = c & 63;
    int am0 = (rem >> 4) * 32, an0 = (rem & 15) * 32;
    // phase B/D tile map: 4 m-tiles x 32 n-tiles(16 wide) = 128 CTAs
    int bm0 = (c >> 5) * 32, bn0 = (c & 31) * 16;
    int brow = tid >> 3, bcolp = (tid & 7) * 2;

    for (int t = 0; t < TT; t++){
        const float* h0prev = (t == 0) ? g_h0 : ((t & 1) ? g_H0a : g_H0b);
        float*       h0cur  = (t & 1) ? g_H0b : g_H0a;
        const float* h1prev = (t == 0) ? g_h0 : g_H1 + (t-1)*BB*HH;
        float*       h1cur  = g_H1 + t*BB*HH;
        const float* XU = g_XU + t*BB*HH;
        const float* XR = g_XR + t*BB*HH;
        const float* XC = g_XC + t*BB*HH;

        // --- Phase A: u0 / r0*h0 (K=512, x-part precomputed) ---
        {
            float acc[2][2];
            mm32(h0prev, h0prev, HH, gate ? Wr0h : Wu0h, am0, an0, tid, As, Bs, acc);
            int m = am0 + ty*2, n = an0 + tx*2;
#pragma unroll
            for (int i = 0; i < 2; i++)
#pragma unroll
                for (int j = 0; j < 2; j++){
                    int idx = (m+i)*HH + (n+j);
                    if (gate == 0){
                        __stcg(&g_u[idx], sigmoidf_(acc[i][j] + XU[idx]));
                    } else {
                        float hv = __ldcg(&h0prev[idx]);
                        __stcg(&g_rh[idx], sigmoidf_(acc[i][j] + XR[idx]) * hv);
                    }
                }
        }
        gsync(my_gen);

        // --- Phase B: c0 + blend -> h0cur ---
        {
            float a0, a1;
            mm16(g_rh, g_rh, HH, Wc0h, bm0, bn0, tid, As, Bs, a0, a1);
            int idx0 = (bm0+brow)*HH + bn0 + bcolp;
            float c0 = tanhf(a0 + XC[idx0]);
            float c1 = tanhf(a1 + XC[idx0+1]);
            float u0 = __ldcg(&g_u[idx0]),     u1 = __ldcg(&g_u[idx0+1]);
            float p0 = __ldcg(&h0prev[idx0]),  p1 = __ldcg(&h0prev[idx0+1]);
            __stcg(&h0cur[idx0],   u0*p0 + (1.f-u0)*c0);
            __stcg(&h0cur[idx0+1], u1*p1 + (1.f-u1)*c1);
        }
        gsync(my_gen);

        // --- Phase C: u1 / r1*h1 (K=1024, A = [h0cur | h1prev]) ---
        {
            float acc[2][2];
            mm32(h0cur, h1prev, EE+HH, gate ? Wr1 : Wu1, am0, an0, tid, As, Bs, acc);
            int m = am0 + ty*2, n = an0 + tx*2;
#pragma unroll
            for (int i = 0; i < 2; i++)
#pragma unroll
                for (int j = 0; j < 2; j++){
                    int idx = (m+i)*HH + (n+j);
                    if (gate == 0){
                        __stcg(&g_u[idx], sigmoidf_(acc[i][j] + bu1[n+j]));
                    } else {
                        float hv = __ldcg(&h1prev[idx]);
                        __stcg(&g_rh[idx], sigmoidf_(acc[i][j] + br1[n+j]) * hv);
                    }
                }
        }
        gsync(my_gen);

        // --- Phase D: c1 + blend -> h1cur (K=1024, A = [h0cur | g_rh]) ---
        {
            float a0, a1;
            mm16(h0cur, g_rh, EE+HH, Wc1, bm0, bn0, tid, As, Bs, a0, a1);
            int idx0 = (bm0+brow)*HH + bn0 + bcolp;
            float c0 = tanhf(a0 + bc1[bn0+bcolp]);
            float c1 = tanhf(a1 + bc1[bn0+bcolp+1]);
            float u0 = __ldcg(&g_u[idx0]),    u1 = __ldcg(&g_u[idx0+1]);
            float p0 = __ldcg(&h1prev[idx0]), p1 = __ldcg(&h1prev[idx0+1]);
            __stcg(&h1cur[idx0],   u0*p0 + (1.f-u0)*c0);
            __stcg(&h1cur[idx0+1], u1*p1 + (1.f-u1)*c1);
        }
        gsync(my_gen);
    }
}

// ---------------- final state copy ------------------------------------------
__global__ void k_copy_final(const float* __restrict__ h0f,
                             const float* __restrict__ h1f,
                             float* __restrict__ out)
{
    int i = blockIdx.x * blockDim.x + threadIdx.x;
    if (i < BB*HH){
        out[i]         = h0f[i];
        out[BB*HH + i] = h1f[i];
    }
}

// ---------------- launch ----------------------------------------------------
extern "C" void kernel_launch(void* const* d_in, const int* in_sizes, int n_in,
                              void* d_out, int out_size)
{
    const float* cnn = (const float*)d_in[0];
    const int*   tok = (const int*)  d_in[1];
    const float* emb = (const float*)d_in[2];
    const float* inW = (const float*)d_in[3];
    const float* inb = (const float*)d_in[4];
    const float* Wu0 = (const float*)d_in[5];
    const float* bu0 = (const float*)d_in[6];
    const float* Wr0 = (const float*)d_in[7];
    const float* br0 = (const float*)d_in[8];
    const float* Wc0 = (const float*)d_in[9];
    const float* bc0 = (const float*)d_in[10];
    const float* Wu1 = (const float*)d_in[11];
    const float* bu1 = (const float*)d_in[12];
    const float* Wr1 = (const float*)d_in[13];
    const float* br1 = (const float*)d_in[14];
    const float* Wc1 = (const float*)d_in[15];
    const float* bc1 = (const float*)d_in[16];
    const float* outW= (const float*)d_in[17];
    const float* outb= (const float*)d_in[18];
    float* out = (float*)d_out;

    float *ph0,*pH0b,*pH1;
    cudaGetSymbolAddress((void**)&ph0,  g_h0);
    cudaGetSymbolAddress((void**)&pH0b, g_H0b);
    cudaGetSymbolAddress((void**)&pH1,  g_H1);

    // h0 = tanh(cnn @ in_W + in_b)
    k_gemm64<1><<<dim3(8, 2), 256>>>(cnn, inW, inb, ph0, 128, 512, 2048, 2048, 512, 512);
    // gather embeddings
    k_gather<<<TT*BB, 128>>>(tok, emb);
    // layer-0 x-projections for ALL timesteps, 3 gates in one launch
    k_prep3<<<dim3(8, 64, 3), 256>>>(Wu0, Wr0, Wc0, bu0, br0, bc0);

    // persistent recurrent kernel (barrier state reset first for graph replay)
    k_reset<<<1, 1>>>();
    const float* Wu0h = Wu0 + (long)EE*HH;
    const float* Wr0h = Wr0 + (long)EE*HH;
    const float* Wc0h = Wc0 + (long)EE*HH;
    k_recurrent<<<NCTA, 256>>>(Wu0h, Wr0h, Wc0h, Wu1, Wr1, Wc1, bu1, br1, bc1);

    // logits for all timesteps in one GEMM: [4096,512] @ [512,10000]
    k_gemm64<2><<<dim3(157, 64), 256>>>(pH1, outW, outb, out,
                                        4096, VV, 512, 512, VV, VV);
    // final_state = [h_layer0_final (t=31 -> g_H0b), h_layer1_final]
    k_copy_final<<<(BB*HH + 255)/256, 256>>>(pH0b, pH1 + (long)(TT-1)*BB*HH,
                                             out + (long)BB*TT*VV);
}

// round 3
// speedup vs baseline: 1.2416x; 1.2202x over previous
#include <cuda_runtime.h>
#include <math.h>

#define BB 128
#define TT 32
#define EE 512
#define HH 512
#define VV 10000
#define CF 2048
#define NCTA 128
#define SW 36

typedef unsigned long long ull;

// ---------------- scratch (device globals; no allocations allowed) ----------
__device__ float g_h0[BB*HH];
__device__ float g_emb[TT*BB*EE];
__device__ float g_XU[TT*BB*HH];
__device__ float g_XR[TT*BB*HH];
__device__ float g_XC[TT*BB*HH];
__device__ float g_H0a[BB*HH];
__device__ float g_H0b[BB*HH];
__device__ float g_H1[TT*BB*HH];
__device__ float g_u[BB*HH];
__device__ float g_rh[BB*HH];
__device__ unsigned g_bar;
__device__ unsigned g_gen;

__device__ __forceinline__ float sigmoidf_(float v){ return 1.f/(1.f+__expf(-v)); }

// packed f32x2 helpers (FFMA2 path — full-rate fp32 on sm_103a)
__device__ __forceinline__ void fma2(ull &acc, ull a, ull b){
    asm("fma.rn.f32x2 %0, %1, %2, %0;" : "+l"(acc) : "l"(a), "l"(b));
}
__device__ __forceinline__ ull dup2(float x){
    ull r; asm("mov.b64 %0, {%1, %1};" : "=l"(r) : "f"(x)); return r;
}
__device__ __forceinline__ float2 unp2(ull v){
    float2 f; asm("mov.b64 {%0, %1}, %2;" : "=f"(f.x), "=f"(f.y) : "l"(v)); return f;
}

// ---------------- embedding gather ------------------------------------------
__global__ void k_gather(const int* __restrict__ tok, const float* __restrict__ emb){
    int row = blockIdx.x;            // t*BB + b
    int t = row >> 7, b = row & 127;
    int v = tok[b*TT + t];
    const float4* src = (const float4*)(emb + (long)v*EE);
    float4* dst = (float4*)(g_emb + (long)row*EE);
    dst[threadIdx.x] = src[threadIdx.x];
}

// ---------------- big fp32 GEMM, 128x64 tile, FFMA2 microkernel -------------
// EPI: 0 plain, 1 tanh, 2 logits remap (row m=t*128+b -> out[b][t][n])
template<int EPI>
__global__ void __launch_bounds__(256)
k_gemmL(const float* __restrict__ A, const float* __restrict__ Bm,
        const float* __restrict__ bias, float* __restrict__ C,
        int M, int N, int K, int lda, int ldb, int ldc)
{
    __shared__ __align__(16) float As[16*132];
    __shared__ __align__(16) float Bs[16*68];
    int tid = threadIdx.x;
    int ty = tid >> 4, tx = tid & 15;
    int m0 = blockIdx.y * 128, n0 = blockIdx.x * 64;
    int ar = tid >> 1, ac = (tid & 1) * 8;      // A loader: row, col-base
    int br = tid >> 4, bc = (tid & 15) * 4;     // B loader
    bool bok = (n0 + bc) < N;

    ull acc[4][4] = {};
    float4 a0, a1, b0;

    // prologue: chunk 0
    a0 = *(const float4*)(A + (long)(m0+ar)*lda + ac);
    a1 = *(const float4*)(A + (long)(m0+ar)*lda + ac + 4);
    b0 = bok ? *(const float4*)(Bm + (long)br*ldb + n0 + bc)
             : make_float4(0.f,0.f,0.f,0.f);
    As[(ac+0)*132+ar]=a0.x; As[(ac+1)*132+ar]=a0.y; As[(ac+2)*132+ar]=a0.z; As[(ac+3)*132+ar]=a0.w;
    As[(ac+4)*132+ar]=a1.x; As[(ac+5)*132+ar]=a1.y; As[(ac+6)*132+ar]=a1.z; As[(ac+7)*132+ar]=a1.w;
    *(float4*)&Bs[br*68+bc] = b0;
    __syncthreads();

    int nch = K >> 4;
    for (int ch = 1; ch <= nch; ch++){
        if (ch < nch){
            int k0 = ch * 16;
            a0 = *(const float4*)(A + (long)(m0+ar)*lda + k0 + ac);
            a1 = *(const float4*)(A + (long)(m0+ar)*lda + k0 + ac + 4);
            b0 = bok ? *(const float4*)(Bm + (long)(k0+br)*ldb + n0 + bc)
                     : make_float4(0.f,0.f,0.f,0.f);
        }
#pragma unroll
        for (int kk = 0; kk < 16; kk++){
            ull av[4];
#pragma unroll
            for (int p = 0; p < 4; p++)
                av[p] = *(const ull*)(As + kk*132 + ty*8 + 2*p);
            float4 bv = *(const float4*)(Bs + kk*68 + tx*4);
            ull bb0 = dup2(bv.x), bb1 = dup2(bv.y), bb2 = dup2(bv.z), bb3 = dup2(bv.w);
#pragma unroll
            for (int p = 0; p < 4; p++){
                fma2(acc[p][0], av[p], bb0);
                fma2(acc[p][1], av[p], bb1);
                fma2(acc[p][2], av[p], bb2);
                fma2(acc[p][3], av[p], bb3);
            }
        }
        if (ch < nch){
            __syncthreads();
            As[(ac+0)*132+ar]=a0.x; As[(ac+1)*132+ar]=a0.y; As[(ac+2)*132+ar]=a0.z; As[(ac+3)*132+ar]=a0.w;
            As[(ac+4)*132+ar]=a1.x; As[(ac+5)*132+ar]=a1.y; As[(ac+6)*132+ar]=a1.z; As[(ac+7)*132+ar]=a1.w;
            *(float4*)&Bs[br*68+bc] = b0;
            __syncthreads();
        }
    }

    // epilogue
#pragma unroll
    for (int p = 0; p < 4; p++){
#pragma unroll
        for (int j = 0; j < 4; j++){
            float2 v = unp2(acc[p][j]);
            int n = n0 + tx*4 + j;
            if (n < N){
                float bz = bias[n];
                float r0 = v.x + bz, r1 = v.y + bz;
                if (EPI == 1){ r0 = tanhf(r0); r1 = tanhf(r1); }
                int row0 = ty*8 + 2*p;
                if (EPI == 2){
                    long base = (long)row0*(TT*(long)VV) + (long)blockIdx.y*VV + n;
                    C[base] = r0;
                    C[base + TT*(long)VV] = r1;
                } else {
                    C[(long)(m0+row0)*ldc + n] = r0;
                    C[(long)(m0+row0+1)*ldc + n] = r1;
                }
            }
        }
    }
}

// ---------------- barrier state reset (per graph replay) --------------------
__global__ void k_reset(){ g_bar = 0u; g_gen = 0u; }

// ---------------- grid-wide sense barrier -----------------------------------
__device__ __forceinline__ void gsync(unsigned &my_gen){
    __syncthreads();
    if (threadIdx.x == 0){
        __threadfence();
        my_gen++;
        if (atomicAdd(&g_bar, 1u) == NCTA-1u){
            atomicExch(&g_bar, 0u);
            __threadfence();
            atomicExch(&g_gen, my_gen);
        } else {
            while (*(volatile unsigned*)&g_gen < my_gen) { }
            __threadfence();
        }
    }
    __syncthreads();
}

// ---------------- phase A/C GEMM: 32x32 tile, 4m x 1n micro, FFMA2 ----------
// A streamed via __ldcg (mutable, L1-bypass), chunked K=64 with reg prefetch.
__device__ __forceinline__ void mmA(const float* __restrict__ Ax,
                                    const float* __restrict__ Ah, int KK,
                                    const float* __restrict__ W,
                                    int m0, int n0, int tid,
                                    float* As, float* Bs, ull &acc0, ull &acc1)
{
    int lr = tid >> 3, lc = (tid & 7) * 4;
    int cn = tid & 31, cm = (tid >> 5) * 4;
    acc0 = 0ull; acc1 = 0ull;
    float4 a0, a1, b0, b1;

    {   // prologue chunk 0
        const float* s0 = (lc      < EE) ? Ax : Ah; int k0c = (lc      < EE) ? lc      : lc-EE;
        const float* s1 = (lc+32   < EE) ? Ax : Ah; int k1c = (lc+32   < EE) ? lc+32   : lc+32-EE;
        a0 = __ldcg((const float4*)(s0 + (m0+lr)*HH + k0c));
        a1 = __ldcg((const float4*)(s1 + (m0+lr)*HH + k1c));
        b0 = *(const float4*)(W + (long)lr*HH + n0 + lc);
        b1 = *(const float4*)(W + (long)(lr+32)*HH + n0 + lc);
    }
    As[(lc+0)*SW+lr]=a0.x; As[(lc+1)*SW+lr]=a0.y; As[(lc+2)*SW+lr]=a0.z; As[(lc+3)*SW+lr]=a0.w;
    As[(lc+32)*SW+lr]=a1.x; As[(lc+33)*SW+lr]=a1.y; As[(lc+34)*SW+lr]=a1.z; As[(lc+35)*SW+lr]=a1.w;
    *(float4*)&Bs[lr*SW+lc] = b0;
    *(float4*)&Bs[(lr+32)*SW+lc] = b1;
    __syncthreads();

    int nch = KK >> 6;
    for (int ch = 1; ch <= nch; ch++){
        if (ch < nch){
            int k0 = ch * 64;
            int ka = k0 + lc, kb = k0 + lc + 32;
            const float* s0 = (ka < EE) ? Ax : Ah; int k0c = (ka < EE) ? ka : ka-EE;
            const float* s1 = (kb < EE) ? Ax : Ah; int k1c = (kb < EE) ? kb : kb-EE;
            a0 = __ldcg((const float4*)(s0 + (m0+lr)*HH + k0c));
            a1 = __ldcg((const float4*)(s1 + (m0+lr)*HH + k1c));
            b0 = *(const float4*)(W + (long)(k0+lr)*HH + n0 + lc);
            b1 = *(const float4*)(W + (long)(k0+lr+32)*HH + n0 + lc);
        }
#pragma unroll
        for (int kk = 0; kk < 64; kk++){
            ull av0 = *(const ull*)(As + kk*SW + cm);
            ull av1 = *(const ull*)(As + kk*SW + cm + 2);
            ull bb  = dup2(Bs[kk*SW + cn]);
            fma2(acc0, av0, bb);
            fma2(acc1, av1, bb);
        }
        if (ch < nch){
            __syncthreads();
            As[(lc+0)*SW+lr]=a0.x; As[(lc+1)*SW+lr]=a0.y; As[(lc+2)*SW+lr]=a0.z; As[(lc+3)*SW+lr]=a0.w;
            As[(lc+32)*SW+lr]=a1.x; As[(lc+33)*SW+lr]=a1.y; As[(lc+34)*SW+lr]=a1.z; As[(lc+35)*SW+lr]=a1.w;
            *(float4*)&Bs[lr*SW+lc] = b0;
            *(float4*)&Bs[(lr+32)*SW+lc] = b1;
            __syncthreads();
        }
    }
}

// ---------------- phase B/D GEMM: 16x32 tile, 1m x 2n micro, FFMA2 ----------
__device__ __forceinline__ void mmB(const float* __restrict__ Ax,
                                    const float* __restrict__ Ah, int KK,
                                    const float* __restrict__ W,
                                    int m0, int n0, int tid,
                                    float* As, float* Bs, ull &acc)
{
    int ar = tid >> 4, ac = (tid & 15) * 4;     // A tile 16x64
    int wr = tid >> 3, wc = (tid & 7) * 4;      // W tile 64x32
    int cm = tid >> 4, cn = (tid & 15) * 2;
    acc = 0ull;
    float4 a0, b0, b1;

    {
        const float* s0 = (ac < EE) ? Ax : Ah; int k0c = (ac < EE) ? ac : ac-EE;
        a0 = __ldcg((const float4*)(s0 + (m0+ar)*HH + k0c));
        b0 = *(const float4*)(W + (long)wr*HH + n0 + wc);
        b1 = *(const float4*)(W + (long)(wr+32)*HH + n0 + wc);
    }
    As[(ac+0)*SW+ar]=a0.x; As[(ac+1)*SW+ar]=a0.y; As[(ac+2)*SW+ar]=a0.z; As[(ac+3)*SW+ar]=a0.w;
    *(float4*)&Bs[wr*SW+wc] = b0;
    *(float4*)&Bs[(wr+32)*SW+wc] = b1;
    __syncthreads();

    int nch = KK >> 6;
    for (int ch = 1; ch <= nch; ch++){
        if (ch < nch){
            int k0 = ch * 64;
            int ka = k0 + ac;
            const float* s0 = (ka < EE) ? Ax : Ah; int k0c = (ka < EE) ? ka : ka-EE;
            a0 = __ldcg((const float4*)(s0 + (m0+ar)*HH + k0c));
            b0 = *(const float4*)(W + (long)(k0+wr)*HH + n0 + wc);
            b1 = *(const float4*)(W + (long)(k0+wr+32)*HH + n0 + wc);
        }
#pragma unroll
        for (int kk = 0; kk < 64; kk++){
            ull ad = dup2(As[kk*SW + cm]);
            ull bv = *(const ull*)(Bs + kk*SW + cn);
            fma2(acc, ad, bv);
        }
        if (ch < nch){
            __syncthreads();
            As[(ac+0)*SW+ar]=a0.x; As[(ac+1)*SW+ar]=a0.y; As[(ac+2)*SW+ar]=a0.z; As[(ac+3)*SW+ar]=a0.w;
            *(float4*)&Bs[wr*SW+wc] = b0;
            *(float4*)&Bs[(wr+32)*SW+wc] = b1;
            __syncthreads();
        }
    }
}

// ---------------- persistent recurrent kernel -------------------------------
__global__ void __launch_bounds__(256, 1)
k_recurrent(const float* __restrict__ Wu0h, const float* __restrict__ Wr0h,
            const float* __restrict__ Wc0h,
            const float* __restrict__ Wu1,  const float* __restrict__ Wr1,
            const float* __restrict__ Wc1,
            const float* __restrict__ bu1,  const float* __restrict__ br1,
            const float* __restrict__ bc1)
{
    __shared__ __align__(16) float As[64*SW];
    __shared__ __align__(16) float Bs[64*SW];
    int tid = threadIdx.x, c = blockIdx.x;
    unsigned my_gen = 0;
    // phase A/C map: 2 gates x 4 m-tiles(32) x 16 n-tiles(32) = 128 CTAs
    int gate = c >> 6, rem = c & 63;
    int am0 = (rem >> 4) * 32, an0 = (rem & 15) * 32;
    // phase B/D map: 8 m-tiles(16) x 16 n-tiles(32) = 128 CTAs
    int bm0 = (c >> 4) * 16, bn0 = (c & 15) * 32;
    int a_cn = tid & 31, a_cm = (tid >> 5) * 4;
    int b_cm = tid >> 4, b_cn = (tid & 15) * 2;

    for (int t = 0; t < TT; t++){
        const float* h0prev = (t == 0) ? g_h0 : ((t & 1) ? g_H0a : g_H0b);
        float*       h0cur  = (t & 1) ? g_H0b : g_H0a;
        const float* h1prev = (t == 0) ? g_h0 : g_H1 + (t-1)*BB*HH;
        float*       h1cur  = g_H1 + t*BB*HH;
        const float* XU = g_XU + t*BB*HH;
        const float* XR = g_XR + t*BB*HH;
        const float* XC = g_XC + t*BB*HH;

        // --- Phase A: u0 / r0*h0 (K=512) ---
        {
            ull acc0, acc1;
            mmA(h0prev, h0prev, HH, gate ? Wr0h : Wu0h, am0, an0, tid, As, Bs, acc0, acc1);
            float2 v0 = unp2(acc0), v1 = unp2(acc1);
            float vv[4] = {v0.x, v0.y, v1.x, v1.y};
            int n = an0 + a_cn;
            if (gate == 0){
#pragma unroll
                for (int i = 0; i < 4; i++){
                    int idx = (am0 + a_cm + i)*HH + n;
                    __stcg(&g_u[idx], sigmoidf_(vv[i] + XU[idx]));
                }
            } else {
#pragma unroll
                for (int i = 0; i < 4; i++){
                    int idx = (am0 + a_cm + i)*HH + n;
                    float hv = __ldcg(&h0prev[idx]);
                    __stcg(&g_rh[idx], sigmoidf_(vv[i] + XR[idx]) * hv);
                }
            }
        }
        gsync(my_gen);

        // --- Phase B: c0 + blend -> h0cur (K=512) ---
        {
            ull acc;
            mmB(g_rh, g_rh, HH, Wc0h, bm0, bn0, tid, As, Bs, acc);
            float2 v = unp2(acc);
            int idx = (bm0 + b_cm)*HH + bn0 + b_cn;
            float c0 = tanhf(v.x + XC[idx]);
            float c1 = tanhf(v.y + XC[idx+1]);
            float2 uu = __ldcg((const float2*)&g_u[idx]);
            float2 pp = __ldcg((const float2*)&h0prev[idx]);
            float2 o;
            o.x = uu.x*pp.x + (1.f-uu.x)*c0;
            o.y = uu.y*pp.y + (1.f-uu.y)*c1;
            __stcg((float2*)&h0cur[idx], o);
        }
        gsync(my_gen);

        // --- Phase C: u1 / r1*h1 (K=1024, A = [h0cur | h1prev]) ---
        {
            ull acc0, acc1;
            mmA(h0cur, h1prev, EE+HH, gate ? Wr1 : Wu1, am0, an0, tid, As, Bs, acc0, acc1);
            float2 v0 = unp2(acc0), v1 = unp2(acc1);
            float vv[4] = {v0.x, v0.y, v1.x, v1.y};
            int n = an0 + a_cn;
            if (gate == 0){
                float bz = bu1[n];
#pragma unroll
                for (int i = 0; i < 4; i++){
                    int idx = (am0 + a_cm + i)*HH + n;
                    __stcg(&g_u[idx], sigmoidf_(vv[i] + bz));
                }
            } else {
                float bz = br1[n];
#pragma unroll
                for (int i = 0; i < 4; i++){
                    int idx = (am0 + a_cm + i)*HH + n;
                    float hv = __ldcg(&h1prev[idx]);
                    __stcg(&g_rh[idx], sigmoidf_(vv[i] + bz) * hv);
                }
            }
        }
        gsync(my_gen);

        // --- Phase D: c1 + blend -> h1cur (K=1024, A = [h0cur | g_rh]) ---
        {
            ull acc;
            mmB(h0cur, g_rh, EE+HH, Wc1, bm0, bn0, tid, As, Bs, acc);
            float2 v = unp2(acc);
            int idx = (bm0 + b_cm)*HH + bn0 + b_cn;
            float c0 = tanhf(v.x + bc1[bn0 + b_cn]);
            float c1 = tanhf(v.y + bc1[bn0 + b_cn + 1]);
            float2 uu = __ldcg((const float2*)&g_u[idx]);
            float2 pp = __ldcg((const float2*)&h1prev[idx]);
            float2 o;
            o.x = uu.x*pp.x + (1.f-uu.x)*c0;
            o.y = uu.y*pp.y + (1.f-uu.y)*c1;
            __stcg((float2*)&h1cur[idx], o);
        }
        gsync(my_gen);
    }
}

// ---------------- final state copy ------------------------------------------
__global__ void k_copy_final(const float* __restrict__ h0f,
                             const float* __restrict__ h1f,
                             float* __restrict__ out)
{
    int i = blockIdx.x * blockDim.x + threadIdx.x;
    if (i < BB*HH){
        out[i]         = h0f[i];
        out[BB*HH + i] = h1f[i];
    }
}

// ---------------- launch ----------------------------------------------------
extern "C" void kernel_launch(void* const* d_in, const int* in_sizes, int n_in,
                              void* d_out, int out_size)
{
    const float* cnn = (const float*)d_in[0];
    const int*   tok = (const int*)  d_in[1];
    const float* emb = (const float*)d_in[2];
    const float* inW = (const float*)d_in[3];
    const float* inb = (const float*)d_in[4];
    const float* Wu0 = (const float*)d_in[5];
    const float* bu0 = (const float*)d_in[6];
    const float* Wr0 = (const float*)d_in[7];
    const float* br0 = (const float*)d_in[8];
    const float* Wc0 = (const float*)d_in[9];
    const float* bc0 = (const float*)d_in[10];
    const float* Wu1 = (const float*)d_in[11];
    const float* bu1 = (const float*)d_in[12];
    const float* Wr1 = (const float*)d_in[13];
    const float* br1 = (const float*)d_in[14];
    const float* Wc1 = (const float*)d_in[15];
    const float* bc1 = (const float*)d_in[16];
    const float* outW= (const float*)d_in[17];
    const float* outb= (const float*)d_in[18];
    float* out = (float*)d_out;

    float *ph0,*pemb,*pXU,*pXR,*pXC,*pH0b,*pH1;
    cudaGetSymbolAddress((void**)&ph0,  g_h0);
    cudaGetSymbolAddress((void**)&pemb, g_emb);
    cudaGetSymbolAddress((void**)&pXU,  g_XU);
    cudaGetSymbolAddress((void**)&pXR,  g_XR);
    cudaGetSymbolAddress((void**)&pXC,  g_XC);
    cudaGetSymbolAddress((void**)&pH0b, g_H0b);
    cudaGetSymbolAddress((void**)&pH1,  g_H1);

    // h0 = tanh(cnn @ in_W + in_b)   [128,2048]@[2048,512]
    k_gemmL<1><<<dim3(8, 1), 256>>>(cnn, inW, inb, ph0, 128, 512, 2048, 2048, 512, 512);
    // gather embeddings
    k_gather<<<TT*BB, 128>>>(tok, emb);
    // layer-0 x-projections for ALL timesteps  [4096,512]@[512,512]
    k_gemmL<0><<<dim3(8, 32), 256>>>(pemb, Wu0, bu0, pXU, 4096, 512, 512, 512, 512, 512);
    k_gemmL<0><<<dim3(8, 32), 256>>>(pemb, Wr0, br0, pXR, 4096, 512, 512, 512, 512, 512);
    k_gemmL<0><<<dim3(8, 32), 256>>>(pemb, Wc0, bc0, pXC, 4096, 512, 512, 512, 512, 512);

    // persistent recurrent kernel
    k_reset<<<1, 1>>>();
    const float* Wu0h = Wu0 + (long)EE*HH;
    const float* Wr0h = Wr0 + (long)EE*HH;
    const float* Wc0h = Wc0 + (long)EE*HH;
    k_recurrent<<<NCTA, 256>>>(Wu0h, Wr0h, Wc0h, Wu1, Wr1, Wc1, bu1, br1, bc1);

    // logits for all timesteps: [4096,512]@[512,10000]
    k_gemmL<2><<<dim3(157, 32), 256>>>(pH1, outW, outb, out,
                                       4096, VV, 512, 512, VV, VV);
    // final_state
    k_copy_final<<<(BB*HH + 255)/256, 256>>>(pH0b, pH1 + (long)(TT-1)*BB*HH,
                                             out + (long)BB*TT*VV);
}

// round 6
// speedup vs baseline: 1.4638x; 1.1790x over previous
#include <cuda_runtime.h>
#include <cuda_bf16.h>
#include <cstdint>
#include <stdint.h>
#include <math.h>

#define BB 128
#define TT 32
#define EE 512
#define HH 512
#define VV 10000
#define CF 2048
#define NCTA 128
#define SW 36
#define VPAD 10112            // 79 n-tiles of 128

#define APITCH 40             // bf16 elements per smem row (80B, conflict-free)
#define TILEB (128*APITCH*2)  // 10240 bytes per tile
#define BUFB (4*TILEB)        // 40960 bytes per buffer

typedef unsigned long long ull;

// ---------------- scratch (device globals; no allocations allowed) ----------
__device__ float g_h0[BB*HH];
__device__ float g_emb[TT*BB*EE];
__device__ float g_XU[TT*BB*HH];
__device__ float g_XR[TT*BB*HH];
__device__ float g_XC[TT*BB*HH];
__device__ float g_H0a[BB*HH];
__device__ float g_H0b[BB*HH];
__device__ float g_H1[TT*BB*HH];
__device__ float g_u[BB*HH];
__device__ float g_rh[BB*HH];
__device__ unsigned g_bar;
__device__ unsigned g_gen;
// bf16 split buffers: row = [hi(512) | lo(512)]
__device__ __nv_bfloat16 g_A2[4096*1024];
__device__ __nv_bfloat16 g_B2[VPAD*1024];

__device__ __forceinline__ float sigmoidf_(float v){ return 1.f/(1.f+__expf(-v)); }

// packed f32x2 helpers (FFMA2 path)
__device__ __forceinline__ void fma2(ull &acc, ull a, ull b){
    asm("fma.rn.f32x2 %0, %1, %2, %0;" : "+l"(acc) : "l"(a), "l"(b));
}
__device__ __forceinline__ ull dup2(float x){
    ull r; asm("mov.b64 %0, {%1, %1};" : "=l"(r) : "f"(x)); return r;
}
__device__ __forceinline__ float2 unp2(ull v){
    float2 f; asm("mov.b64 {%0, %1}, %2;" : "=f"(f.x), "=f"(f.y) : "l"(v)); return f;
}

// ---------------- mma.sync helpers (base sm_103-legal) ----------------------
__device__ __forceinline__ uint32_t smem_u32(const void* p){
    uint32_t a;
    asm("{ .reg .u64 t; cvta.to.shared.u64 t, %1; cvt.u32.u64 %0, t; }" : "=r"(a) : "l"(p));
    return a;
}
__device__ __forceinline__ void cpa16(uint32_t dst, const void* src){
    asm volatile("cp.async.cg.shared.global [%0], [%1], 16;" :: "r"(dst), "l"(src));
}
__device__ __forceinline__ void cpa_commit(){
    asm volatile("cp.async.commit_group;" ::: "memory");
}
template<int N> __device__ __forceinline__ void cpa_wait(){
    asm volatile("cp.async.wait_group %0;" :: "n"(N) : "memory");
}
__device__ __forceinline__ void ldx4(uint32_t* r, uint32_t addr){
    asm volatile("ldmatrix.sync.aligned.m8n8.x4.shared.b16 {%0,%1,%2,%3}, [%4];"
        : "=r"(r[0]), "=r"(r[1]), "=r"(r[2]), "=r"(r[3]) : "r"(addr));
}
__device__ __forceinline__ void mma16816(float* d, const uint32_t* a,
                                         uint32_t b0, uint32_t b1){
    asm volatile("mma.sync.aligned.m16n8k16.row.col.f32.bf16.bf16.f32 "
        "{%0,%1,%2,%3}, {%4,%5,%6,%7}, {%8,%9}, {%0,%1,%2,%3};"
        : "+f"(d[0]), "+f"(d[1]), "+f"(d[2]), "+f"(d[3])
        : "r"(a[0]), "r"(a[1]), "r"(a[2]), "r"(a[3]), "r"(b0), "r"(b1));
}

// ---------------- embedding gather ------------------------------------------
__global__ void k_gather(const int* __restrict__ tok, const float* __restrict__ emb){
    int row = blockIdx.x;            // t*BB + b
    int t = row >> 7, b = row & 127;
    int v = tok[b*TT + t];
    const float4* src = (const float4*)(emb + (long)v*EE);
    float4* dst = (float4*)(g_emb + (long)row*EE);
    dst[threadIdx.x] = src[threadIdx.x];
}

// ---------------- big fp32 GEMM, 128x64 tile, FFMA2 (prep + h0) -------------
template<int EPI>
__global__ void __launch_bounds__(256)
k_gemmL(const float* __restrict__ A, const float* __restrict__ Bm,
        const float* __restrict__ bias, float* __restrict__ C,
        int M, int N, int K, int lda, int ldb, int ldc)
{
    __shared__ __align__(16) float As[16*132];
    __shared__ __align__(16) float Bs[16*68];
    int tid = threadIdx.x;
    int ty = tid >> 4, tx = tid & 15;
    int m0 = blockIdx.y * 128, n0 = blockIdx.x * 64;
    int ar = tid >> 1, ac = (tid & 1) * 8;
    int br = tid >> 4, bc = (tid & 15) * 4;
    bool bok = (n0 + bc) < N;

    ull acc[4][4] = {};
    float4 a0, a1, b0;

    a0 = *(const float4*)(A + (long)(m0+ar)*lda + ac);
    a1 = *(const float4*)(A + (long)(m0+ar)*lda + ac + 4);
    b0 = bok ? *(const float4*)(Bm + (long)br*ldb + n0 + bc)
             : make_float4(0.f,0.f,0.f,0.f);
    As[(ac+0)*132+ar]=a0.x; As[(ac+1)*132+ar]=a0.y; As[(ac+2)*132+ar]=a0.z; As[(ac+3)*132+ar]=a0.w;
    As[(ac+4)*132+ar]=a1.x; As[(ac+5)*132+ar]=a1.y; As[(ac+6)*132+ar]=a1.z; As[(ac+7)*132+ar]=a1.w;
    *(float4*)&Bs[br*68+bc] = b0;
    __syncthreads();

    int nch = K >> 4;
    for (int ch = 1; ch <= nch; ch++){
        if (ch < nch){
            int k0 = ch * 16;
            a0 = *(const float4*)(A + (long)(m0+ar)*lda + k0 + ac);
            a1 = *(const float4*)(A + (long)(m0+ar)*lda + k0 + ac + 4);
            b0 = bok ? *(const float4*)(Bm + (long)(k0+br)*ldb + n0 + bc)
                     : make_float4(0.f,0.f,0.f,0.f);
        }
#pragma unroll
        for (int kk = 0; kk < 16; kk++){
            ull av[4];
#pragma unroll
            for (int p = 0; p < 4; p++)
                av[p] = *(const ull*)(As + kk*132 + ty*8 + 2*p);
            float4 bv = *(const float4*)(Bs + kk*68 + tx*4);
            ull bb0 = dup2(bv.x), bb1 = dup2(bv.y), bb2 = dup2(bv.z), bb3 = dup2(bv.w);
#pragma unroll
            for (int p = 0; p < 4; p++){
                fma2(acc[p][0], av[p], bb0);
                fma2(acc[p][1], av[p], bb1);
                fma2(acc[p][2], av[p], bb2);
                fma2(acc[p][3], av[p], bb3);
            }
        }
        if (ch < nch){
            __syncthreads();
            As[(ac+0)*132+ar]=a0.x; As[(ac+1)*132+ar]=a0.y; As[(ac+2)*132+ar]=a0.z; As[(ac+3)*132+ar]=a0.w;
            As[(ac+4)*132+ar]=a1.x; As[(ac+5)*132+ar]=a1.y; As[(ac+6)*132+ar]=a1.z; As[(ac+7)*132+ar]=a1.w;
            *(float4*)&Bs[br*68+bc] = b0;
            __syncthreads();
        }
    }

#pragma unroll
    for (int p = 0; p < 4; p++){
#pragma unroll
        for (int j = 0; j < 4; j++){
            float2 v = unp2(acc[p][j]);
            int n = n0 + tx*4 + j;
            if (n < N){
                float bz = bias[n];
                float r0 = v.x + bz, r1 = v.y + bz;
                if (EPI == 1){ r0 = tanhf(r0); r1 = tanhf(r1); }
                int row0 = ty*8 + 2*p;
                C[(long)(m0+row0)*ldc + n] = r0;
                C[(long)(m0+row0+1)*ldc + n] = r1;
            }
        }
    }
}

// ---------------- bf16 split packers ----------------------------------------
// A: g_H1 [4096,512] -> g_A2 rows [hi512 | lo512]
__global__ void k_packA(){
    int g = blockIdx.x * blockDim.x + threadIdx.x;
    int m = g >> 9, k = g & 511;
    float v = g_H1[g];
    __nv_bfloat16 hi = __float2bfloat16(v);
    __nv_bfloat16 lo = __float2bfloat16(v - __bfloat162float(hi));
    g_A2[(long)m*1024 + k]       = hi;
    g_A2[(long)m*1024 + 512 + k] = lo;
}

// B: out_W [512,10000] transposed -> g_B2 [VPAD rows][hi512|lo512], pad zero
__global__ void k_packB(const float* __restrict__ W){
    __shared__ float tile[32][65];
    int n0 = blockIdx.x * 64, k0 = blockIdx.y * 32;
    int tid = threadIdx.x;
#pragma unroll
    for (int p = 0; p < 8; p++){
        int idx = tid + p*256;
        int kk = idx >> 6, nn = idx & 63;
        int n = n0 + nn;
        tile[kk][nn] = (n < VV) ? W[(long)(k0+kk)*VV + n] : 0.f;
    }
    __syncthreads();
#pragma unroll
    for (int p = 0; p < 8; p++){
        int idx = tid + p*256;
        int nn = idx >> 5, kk = idx & 31;
        float v = tile[kk][nn];
        __nv_bfloat16 hi = __float2bfloat16(v);
        __nv_bfloat16 lo = __float2bfloat16(v - __bfloat162float(hi));
        long base = (long)(n0+nn)*1024 + k0 + kk;
        g_B2[base]       = hi;
        g_B2[base + 512] = lo;
    }
}

// ---------------- mma.sync bf16 logits GEMM ---------------------------------
// D = H1 @ outW + b via 3-term split; 128x128 tile/CTA, 8 warps (2m x 4n)
__global__ void __launch_bounds__(256)
k_logits_mma(const float* __restrict__ bias, float* __restrict__ out)
{
    extern __shared__ __align__(16) char dsm[];
    int tid = threadIdx.x, lane = tid & 31, wid = tid >> 5;
    int t = blockIdx.y;                 // m-tile index == timestep
    int n0 = blockIdx.x * 128;
    int wm = (wid & 1) * 64, wn = (wid >> 1) * 32;

    const __nv_bfloat16* Abase = g_A2 + (long)t*128*1024;
    const __nv_bfloat16* Bbase = g_B2 + (long)n0*1024;
    uint32_t sbase = smem_u32(dsm);

    float acc[4][4][4];
#pragma unroll
    for (int i = 0; i < 4; i++)
#pragma unroll
        for (int j = 0; j < 4; j++)
#pragma unroll
            for (int q = 0; q < 4; q++) acc[i][j][q] = 0.f;

    // ldmatrix source offsets (elements)
    int aoff = (wm + (lane & 15)) * APITCH + (lane >> 4) * 8;
    int boff = (wn + (lane & 7) + ((lane >> 4) << 3)) * APITCH + ((lane >> 3) & 1) * 8;

    auto load_chunk = [&](int c, int bi){
        int k0 = c * 32;
        uint32_t bu = sbase + bi * BUFB;
#pragma unroll
        for (int it = 0; it < 8; it++){
            int e = tid + it * 256;       // 0..2047
            int tile = e >> 9;            // 0=Ah 1=Al 2=Bh 3=Bl
            int r = (e >> 2) & 127;
            int seg = e & 3;
            const __nv_bfloat16* src =
                (tile < 2 ? Abase : Bbase) + (long)r*1024 + ((tile & 1) ? 512 : 0) + k0 + seg*8;
            cpa16(bu + tile*TILEB + (r*APITCH + seg*8)*2, src);
        }
        cpa_commit();
    };

    load_chunk(0, 0);
    for (int c = 0; c < 16; c++){
        if (c + 1 < 16){ load_chunk(c+1, (c+1) & 1); cpa_wait<1>(); }
        else           { cpa_wait<0>(); }
        __syncthreads();
        uint32_t bu = sbase + (c & 1) * BUFB;
        uint32_t uAh = bu, uAl = bu + TILEB, uBh = bu + 2*TILEB, uBl = bu + 3*TILEB;
#pragma unroll
        for (int ks = 0; ks < 2; ks++){
            uint32_t ah[4][4], al[4][4], bh[2][4], bl[2][4];
#pragma unroll
            for (int mi = 0; mi < 4; mi++){
                uint32_t ao = (uint32_t)(aoff + mi*16*APITCH + ks*16) * 2;
                ldx4(ah[mi], uAh + ao);
                ldx4(al[mi], uAl + ao);
            }
#pragma unroll
            for (int p = 0; p < 2; p++){
                uint32_t bo = (uint32_t)(boff + p*16*APITCH + ks*16) * 2;
                ldx4(bh[p], uBh + bo);
                ldx4(bl[p], uBl + bo);
            }
#pragma unroll
            for (int mi = 0; mi < 4; mi++)
#pragma unroll
                for (int nj = 0; nj < 4; nj++){
                    int p = nj >> 1, q = (nj & 1) * 2;
                    mma16816(acc[mi][nj], ah[mi], bh[p][q], bh[p][q+1]);
                    mma16816(acc[mi][nj], al[mi], bh[p][q], bh[p][q+1]);
                    mma16816(acc[mi][nj], ah[mi], bl[p][q], bl[p][q+1]);
                }
        }
        __syncthreads();
    }

    // epilogue: d0,d1 -> (row lr, n, n+1); d2,d3 -> row lr+8
    int lr = lane >> 2, lc = (lane & 3) * 2;
    long strideB = TT * (long)VV;
#pragma unroll
    for (int mi = 0; mi < 4; mi++){
        int b0 = wm + mi*16 + lr;               // local row = batch index
        long base0 = (long)b0*strideB + (long)t*VV;
#pragma unroll
        for (int nj = 0; nj < 4; nj++){
            int n = n0 + wn + nj*8 + lc;
            const float* a4 = acc[mi][nj];
            if (n < VV){
                float bz = bias[n];
                out[base0 + n]               = a4[0] + bz;
                out[base0 + 8*strideB + n]   = a4[2] + bz;
            }
            if (n + 1 < VV){
                float bz = bias[n+1];
                out[base0 + n + 1]             = a4[1] + bz;
                out[base0 + 8*strideB + n + 1] = a4[3] + bz;
            }
        }
    }
}

// ---------------- barrier state reset (per graph replay) --------------------
__global__ void k_reset(){ g_bar = 0u; g_gen = 0u; }

// ---------------- grid-wide sense barrier -----------------------------------
__device__ __forceinline__ void gsync(unsigned &my_gen){
    __syncthreads();
    if (threadIdx.x == 0){
        __threadfence();
        my_gen++;
        if (atomicAdd(&g_bar, 1u) == NCTA-1u){
            atomicExch(&g_bar, 0u);
            __threadfence();
            atomicExch(&g_gen, my_gen);
        } else {
            while (*(volatile unsigned*)&g_gen < my_gen) { }
            __threadfence();
        }
    }
    __syncthreads();
}

// ---------------- phase A/C GEMM: 32x32 tile, 4m x 1n micro, FFMA2 ----------
__device__ __forceinline__ void mmA(const float* __restrict__ Ax,
                                    const float* __restrict__ Ah, int KK,
                                    const float* __restrict__ W,
                                    int m0, int n0, int tid,
                                    float* As, float* Bs, ull &acc0, ull &acc1)
{
    int lr = tid >> 3, lc = (tid & 7) * 4;
    int cn = tid & 31, cm = (tid >> 5) * 4;
    acc0 = 0ull; acc1 = 0ull;
    float4 a0, a1, b0, b1;

    {
        const float* s0 = (lc      < EE) ? Ax : Ah; int k0c = (lc      < EE) ? lc      : lc-EE;
        const float* s1 = (lc+32   < EE) ? Ax : Ah; int k1c = (lc+32   < EE) ? lc+32   : lc+32-EE;
        a0 = __ldcg((const float4*)(s0 + (m0+lr)*HH + k0c));
        a1 = __ldcg((const float4*)(s1 + (m0+lr)*HH + k1c));
        b0 = *(const float4*)(W + (long)lr*HH + n0 + lc);
        b1 = *(const float4*)(W + (long)(lr+32)*HH + n0 + lc);
    }
    As[(lc+0)*SW+lr]=a0.x; As[(lc+1)*SW+lr]=a0.y; As[(lc+2)*SW+lr]=a0.z; As[(lc+3)*SW+lr]=a0.w;
    As[(lc+32)*SW+lr]=a1.x; As[(lc+33)*SW+lr]=a1.y; As[(lc+34)*SW+lr]=a1.z; As[(lc+35)*SW+lr]=a1.w;
    *(float4*)&Bs[lr*SW+lc] = b0;
    *(float4*)&Bs[(lr+32)*SW+lc] = b1;
    __syncthreads();

    int nch = KK >> 6;
    for (int ch = 1; ch <= nch; ch++){
        if (ch < nch){
            int k0 = ch * 64;
            int ka = k0 + lc, kb = k0 + lc + 32;
            const float* s0 = (ka < EE) ? Ax : Ah; int k0c = (ka < EE) ? ka : ka-EE;
            const float* s1 = (kb < EE) ? Ax : Ah; int k1c = (kb < EE) ? kb : kb-EE;
            a0 = __ldcg((const float4*)(s0 + (m0+lr)*HH + k0c));
            a1 = __ldcg((const float4*)(s1 + (m0+lr)*HH + k1c));
            b0 = *(const float4*)(W + (long)(k0+lr)*HH + n0 + lc);
            b1 = *(const float4*)(W + (long)(k0+lr+32)*HH + n0 + lc);
        }
#pragma unroll
        for (int kk = 0; kk < 64; kk++){
            ull av0 = *(const ull*)(As + kk*SW + cm);
            ull av1 = *(const ull*)(As + kk*SW + cm + 2);
            ull bb  = dup2(Bs[kk*SW + cn]);
            fma2(acc0, av0, bb);
            fma2(acc1, av1, bb);
        }
        if (ch < nch){
            __syncthreads();
            As[(lc+0)*SW+lr]=a0.x; As[(lc+1)*SW+lr]=a0.y; As[(lc+2)*SW+lr]=a0.z; As[(lc+3)*SW+lr]=a0.w;
            As[(lc+32)*SW+lr]=a1.x; As[(lc+33)*SW+lr]=a1.y; As[(lc+34)*SW+lr]=a1.z; As[(lc+35)*SW+lr]=a1.w;
            *(float4*)&Bs[lr*SW+lc] = b0;
            *(float4*)&Bs[(lr+32)*SW+lc] = b1;
            __syncthreads();
        }
    }
}

// ---------------- phase B/D GEMM: 16x32 tile, 1m x 2n micro, FFMA2 ----------
__device__ __forceinline__ void mmB(const float* __restrict__ Ax,
                                    const float* __restrict__ Ah, int KK,
                                    const float* __restrict__ W,
                                    int m0, int n0, int tid,
                                    float* As, float* Bs, ull &acc)
{
    int ar = tid >> 4, ac = (tid & 15) * 4;
    int wr = tid >> 3, wc = (tid & 7) * 4;
    int cm = tid >> 4, cn = (tid & 15) * 2;
    acc = 0ull;
    float4 a0, b0, b1;

    {
        const float* s0 = (ac < EE) ? Ax : Ah; int k0c = (ac < EE) ? ac : ac-EE;
        a0 = __ldcg((const float4*)(s0 + (m0+ar)*HH + k0c));
        b0 = *(const float4*)(W + (long)wr*HH + n0 + wc);
        b1 = *(const float4*)(W + (long)(wr+32)*HH + n0 + wc);
    }
    As[(ac+0)*SW+ar]=a0.x; As[(ac+1)*SW+ar]=a0.y; As[(ac+2)*SW+ar]=a0.z; As[(ac+3)*SW+ar]=a0.w;
    *(float4*)&Bs[wr*SW+wc] = b0;
    *(float4*)&Bs[(wr+32)*SW+wc] = b1;
    __syncthreads();

    int nch = KK >> 6;
    for (int ch = 1; ch <= nch; ch++){
        if (ch < nch){
            int k0 = ch * 64;
            int ka = k0 + ac;
            const float* s0 = (ka < EE) ? Ax : Ah; int k0c = (ka < EE) ? ka : ka-EE;
            a0 = __ldcg((const float4*)(s0 + (m0+ar)*HH + k0c));
            b0 = *(const float4*)(W + (long)(k0+wr)*HH + n0 + wc);
            b1 = *(const float4*)(W + (long)(k0+wr+32)*HH + n0 + wc);
        }
#pragma unroll
        for (int kk = 0; kk < 64; kk++){
            ull ad = dup2(As[kk*SW + cm]);
            ull bv = *(const ull*)(Bs + kk*SW + cn);
            fma2(acc, ad, bv);
        }
        if (ch < nch){
            __syncthreads();
            As[(ac+0)*SW+ar]=a0.x; As[(ac+1)*SW+ar]=a0.y; As[(ac+2)*SW+ar]=a0.z; As[(ac+3)*SW+ar]=a0.w;
            *(float4*)&Bs[wr*SW+wc] = b0;
            *(float4*)&Bs[(wr+32)*SW+wc] = b1;
            __syncthreads();
        }
    }
}

// ---------------- persistent recurrent kernel -------------------------------
__global__ void __launch_bounds__(256, 1)
k_recurrent(const float* __restrict__ Wu0h, const float* __restrict__ Wr0h,
            const float* __restrict__ Wc0h,
            const float* __restrict__ Wu1,  const float* __restrict__ Wr1,
            const float* __restrict__ Wc1,
            const float* __restrict__ bu1,  const float* __restrict__ br1,
            const float* __restrict__ bc1)
{
    __shared__ __align__(16) float As[64*SW];
    __shared__ __align__(16) float Bs[64*SW];
    int tid = threadIdx.x, c = blockIdx.x;
    unsigned my_gen = 0;
    int gate = c >> 6, rem = c & 63;
    int am0 = (rem >> 4) * 32, an0 = (rem & 15) * 32;
    int bm0 = (c >> 4) * 16, bn0 = (c & 15) * 32;
    int a_cn = tid & 31, a_cm = (tid >> 5) * 4;
    int b_cm = tid >> 4, b_cn = (tid & 15) * 2;

    for (int t = 0; t < TT; t++){
        const float* h0prev = (t == 0) ? g_h0 : ((t & 1) ? g_H0a : g_H0b);
        float*       h0cur  = (t & 1) ? g_H0b : g_H0a;
        const float* h1prev = (t == 0) ? g_h0 : g_H1 + (t-1)*BB*HH;
        float*       h1cur  = g_H1 + t*BB*HH;
        const float* XU = g_XU + t*BB*HH;
        const float* XR = g_XR + t*BB*HH;
        const float* XC = g_XC + t*BB*HH;

        {
            ull acc0, acc1;
            mmA(h0prev, h0prev, HH, gate ? Wr0h : Wu0h, am0, an0, tid, As, Bs, acc0, acc1);
            float2 v0 = unp2(acc0), v1 = unp2(acc1);
            float vv[4] = {v0.x, v0.y, v1.x, v1.y};
            int n = an0 + a_cn;
            if (gate == 0){
#pragma unroll
                for (int i = 0; i < 4; i++){
                    int idx = (am0 + a_cm + i)*HH + n;
                    __stcg(&g_u[idx], sigmoidf_(vv[i] + XU[idx]));
                }
            } else {
#pragma unroll
                for (int i = 0; i < 4; i++){
                    int idx = (am0 + a_cm + i)*HH + n;
                    float hv = __ldcg(&h0prev[idx]);
                    __stcg(&g_rh[idx], sigmoidf_(vv[i] + XR[idx]) * hv);
                }
            }
        }
        gsync(my_gen);

        {
            ull acc;
            mmB(g_rh, g_rh, HH, Wc0h, bm0, bn0, tid, As, Bs, acc);
            float2 v = unp2(acc);
            int idx = (bm0 + b_cm)*HH + bn0 + b_cn;
            float c0 = tanhf(v.x + XC[idx]);
            float c1 = tanhf(v.y + XC[idx+1]);
            float2 uu = __ldcg((const float2*)&g_u[idx]);
            float2 pp = __ldcg((const float2*)&h0prev[idx]);
            float2 o;
            o.x = uu.x*pp.x + (1.f-uu.x)*c0;
            o.y = uu.y*pp.y + (1.f-uu.y)*c1;
            __stcg((float2*)&h0cur[idx], o);
        }
        gsync(my_gen);

        {
            ull acc0, acc1;
            mmA(h0cur, h1prev, EE+HH, gate ? Wr1 : Wu1, am0, an0, tid, As, Bs, acc0, acc1);
            float2 v0 = unp2(acc0), v1 = unp2(acc1);
            float vv[4] = {v0.x, v0.y, v1.x, v1.y};
            int n = an0 + a_cn;
            if (gate == 0){
                float bz = bu1[n];
#pragma unroll
                for (int i = 0; i < 4; i++){
                    int idx = (am0 + a_cm + i)*HH + n;
                    __stcg(&g_u[idx], sigmoidf_(vv[i] + bz));
                }
            } else {
                float bz = br1[n];
#pragma unroll
                for (int i = 0; i < 4; i++){
                    int idx = (am0 + a_cm + i)*HH + n;
                    float hv = __ldcg(&h1prev[idx]);
                    __stcg(&g_rh[idx], sigmoidf_(vv[i] + bz) * hv);
                }
            }
        }
        gsync(my_gen);

        {
            ull acc;
            mmB(h0cur, g_rh, EE+HH, Wc1, bm0, bn0, tid, As, Bs, acc);
            float2 v = unp2(acc);
            int idx = (bm0 + b_cm)*HH + bn0 + b_cn;
            float c0 = tanhf(v.x + bc1[bn0 + b_cn]);
            float c1 = tanhf(v.y + bc1[bn0 + b_cn + 1]);
            float2 uu = __ldcg((const float2*)&g_u[idx]);
            float2 pp = __ldcg((const float2*)&h1prev[idx]);
            float2 o;
            o.x = uu.x*pp.x + (1.f-uu.x)*c0;
            o.y = uu.y*pp.y + (1.f-uu.y)*c1;
            __stcg((float2*)&h1cur[idx], o);
        }
        gsync(my_gen);
    }
}

// ---------------- final state copy ------------------------------------------
__global__ void k_copy_final(const float* __restrict__ h0f,
                             const float* __restrict__ h1f,
                             float* __restrict__ out)
{
    int i = blockIdx.x * blockDim.x + threadIdx.x;
    if (i < BB*HH){
        out[i]         = h0f[i];
        out[BB*HH + i] = h1f[i];
    }
}

// ---------------- launch ----------------------------------------------------
extern "C" void kernel_launch(void* const* d_in, const int* in_sizes, int n_in,
                              void* d_out, int out_size)
{
    const float* cnn = (const float*)d_in[0];
    const int*   tok = (const int*)  d_in[1];
    const float* emb = (const float*)d_in[2];
    const float* inW = (const float*)d_in[3];
    const float* inb = (const float*)d_in[4];
    const float* Wu0 = (const float*)d_in[5];
    const float* bu0 = (const float*)d_in[6];
    const float* Wr0 = (const float*)d_in[7];
    const float* br0 = (const float*)d_in[8];
    const float* Wc0 = (const float*)d_in[9];
    const float* bc0 = (const float*)d_in[10];
    const float* Wu1 = (const float*)d_in[11];
    const float* bu1 = (const float*)d_in[12];
    const float* Wr1 = (const float*)d_in[13];
    const float* br1 = (const float*)d_in[14];
    const float* Wc1 = (const float*)d_in[15];
    const float* bc1 = (const float*)d_in[16];
    const float* outW= (const float*)d_in[17];
    const float* outb= (const float*)d_in[18];
    float* out = (float*)d_out;

    float *ph0,*pemb,*pXU,*pXR,*pXC,*pH0b,*pH1;
    cudaGetSymbolAddress((void**)&ph0,  g_h0);
    cudaGetSymbolAddress((void**)&pemb, g_emb);
    cudaGetSymbolAddress((void**)&pXU,  g_XU);
    cudaGetSymbolAddress((void**)&pXR,  g_XR);
    cudaGetSymbolAddress((void**)&pXC,  g_XC);
    cudaGetSymbolAddress((void**)&pH0b, g_H0b);
    cudaGetSymbolAddress((void**)&pH1,  g_H1);

    // opt-in dynamic smem for the mma logits kernel (host-side attr, capture-safe)
    cudaFuncSetAttribute(k_logits_mma, cudaFuncAttributeMaxDynamicSharedMemorySize, 2*BUFB);

    // h0 = tanh(cnn @ in_W + in_b)
    k_gemmL<1><<<dim3(8, 1), 256>>>(cnn, inW, inb, ph0, 128, 512, 2048, 2048, 512, 512);
    // gather embeddings
    k_gather<<<TT*BB, 128>>>(tok, emb);
    // out_W bf16 split + transpose (independent of recurrent; done early)
    k_packB<<<dim3(VPAD/64, 16), 256>>>(outW);
    // layer-0 x-projections for ALL timesteps
    k_gemmL<0><<<dim3(8, 32), 256>>>(pemb, Wu0, bu0, pXU, 4096, 512, 512, 512, 512, 512);
    k_gemmL<0><<<dim3(8, 32), 256>>>(pemb, Wr0, br0, pXR, 4096, 512, 512, 512, 512, 512);
    k_gemmL<0><<<dim3(8, 32), 256>>>(pemb, Wc0, bc0, pXC, 4096, 512, 512, 512, 512, 512);

    // persistent recurrent kernel
    k_reset<<<1, 1>>>();
    const float* Wu0h = Wu0 + (long)EE*HH;
    const float* Wr0h = Wr0 + (long)EE*HH;
    const float* Wc0h = Wc0 + (long)EE*HH;
    k_recurrent<<<NCTA, 256>>>(Wu0h, Wr0h, Wc0h, Wu1, Wr1, Wc1, bu1, br1, bc1);

    // H1 bf16 split, then tensor-core logits: [4096,512]@[512,10000]
    k_packA<<<4096*512/256, 256>>>();
    k_logits_mma<<<dim3(VPAD/128, 32), 256, 2*BUFB>>>(outb, out);

    // final_state
    k_copy_final<<<(BB*HH + 255)/256, 256>>>(pH0b, pH1 + (long)(TT-1)*BB*HH,
                                             out + (long)BB*TT*VV);
}